// round 14
// baseline (speedup 1.0000x reference)
#include <cuda_runtime.h>
#include <cuda_bf16.h>
#include <cstdint>

#define N_NODES 50000
#define N_EDGES 800000
#define D_IN 128
#define N_HEADS 8
#define PER_HEAD 16
#define LEAKY_ALPHA 0.2f

// ---------------- static device scratch (no allocations allowed) ------------
__device__ float g_q[(size_t)N_NODES * 128];         // 25.6 MB
__device__ float g_k[(size_t)N_NODES * 128];         // 25.6 MB
__device__ int   g_count[N_NODES];                   // in-degree histogram
__device__ int   g_offset[N_NODES + 1];              // CSR row offsets
__device__ int   g_cursor[N_NODES];                  // scatter cursors
__device__ int   g_src_sorted[N_EDGES];              // src node per CSR slot

__device__ __forceinline__ float lrelu(float v) {
    return v > 0.0f ? v : LEAKY_ALPHA * v;
}

__device__ __forceinline__ uint32_t f2tf32(float f) {
    uint32_t r;
    asm("cvt.rna.tf32.f32 %0, %1;" : "=r"(r) : "f"(f));
    return r;
}

__device__ __forceinline__ void mma_tf32(float c[4],
                                         uint32_t a0, uint32_t a1, uint32_t a2, uint32_t a3,
                                         uint32_t b0, uint32_t b1) {
    asm volatile(
        "mma.sync.aligned.m16n8k8.row.col.f32.tf32.tf32.f32 "
        "{%0,%1,%2,%3}, {%4,%5,%6,%7}, {%8,%9}, {%0,%1,%2,%3};"
        : "+f"(c[0]), "+f"(c[1]), "+f"(c[2]), "+f"(c[3])
        : "r"(a0), "r"(a1), "r"(a2), "r"(a3), "r"(b0), "r"(b1));
}

// ---------------- Kernel 1: Q/K GEMM on tensor cores, N-split for 3 CTAs/SM --
// blockIdx.y in 0..3 = (Wq/Wk) x (64-col half). ws = [128][72] tf32 (36.9KB,
// stride 72 == 8 mod 32 -> B-frag banks 8*tid4+g unique); xs = [64][132] tf32
// (33.8KB, A-frag banks 4g+tid4 unique). Total ~71KB -> 3 CTAs/SM (vs R13's 2)
// so three anti-phased CTAs overlap staging with mma. Warp = 16 rows x 32 cols
// = 4 (m16n8k8) n-tiles x 16 k-steps; fp32 accumulate + fp32 bias epilogue.
#define GEMM_BLOCK 256
#define GEMM_TILE_N 64
#define WS_STRIDE 72
#define XS_STRIDE 132
#define N_NODE_TILES ((N_NODES + GEMM_TILE_N - 1) / GEMM_TILE_N)  // 782
#define GEMM_GRID_X 111

__global__ void __launch_bounds__(GEMM_BLOCK, 3)
qk_gemm_tc_kernel(const float* __restrict__ x,
                  const float* __restrict__ wq, const float* __restrict__ bq,
                  const float* __restrict__ wk, const float* __restrict__ bk) {
    extern __shared__ uint32_t smem_u[];
    uint32_t* ws = smem_u;                          // [128][72] = 9216 words
    uint32_t* xs = smem_u + 128 * WS_STRIDE;        // [64][132] = 8448 words
    float* bs = (float*)(xs + GEMM_TILE_N * XS_STRIDE);  // 64 floats

    const int t = threadIdx.x;
    const bool is_q = ((blockIdx.y >> 1) == 0);
    const int wcol0 = (blockIdx.y & 1) * 64;        // column half within W
    const float* wsrc = is_q ? wq : wk;
    const float* bsrc = is_q ? bq : bk;
    float* gout = is_q ? g_q : g_k;

    // stage 128x64 weight half as tf32 (once per block; coalesced)
    for (int i = t; i < 128 * 64; i += GEMM_BLOCK) {
        int k = i >> 6, c = i & 63;
        ws[k * WS_STRIDE + c] = f2tf32(wsrc[k * 128 + wcol0 + c]);
    }
    if (t < 64) bs[t] = bsrc[wcol0 + t];

    const int warp = t >> 5;
    const int lane = t & 31;
    const int g = lane >> 2;          // groupID 0..7
    const int tid4 = lane & 3;        // threadID_in_group 0..3
    const int mb = (warp & 3) * 16;   // warp row base within 64
    const int nb = (warp >> 2) * 32;  // warp col base within 64 (0 or 32)

    for (int tile = blockIdx.x; tile < N_NODE_TILES; tile += gridDim.x) {
        const int n0 = tile * GEMM_TILE_N;
        __syncthreads();   // previous compute done (and joins weight staging)
        // stage 64 nodes x 128 dims -> tf32 (float4 read, uint4 write)
        for (int i = t; i < GEMM_TILE_N * 32; i += GEMM_BLOCK) {
            int n = i >> 5, c4 = i & 31;
            int gn = n0 + n;
            float4 v = make_float4(0.f, 0.f, 0.f, 0.f);
            if (gn < N_NODES) v = *(const float4*)(x + (size_t)gn * 128 + c4 * 4);
            uint4 u;
            u.x = f2tf32(v.x); u.y = f2tf32(v.y);
            u.z = f2tf32(v.z); u.w = f2tf32(v.w);
            *(uint4*)(xs + n * XS_STRIDE + c4 * 4) = u;
        }
        __syncthreads();

        float acc[4][4];
#pragma unroll
        for (int nt = 0; nt < 4; nt++)
#pragma unroll
            for (int c = 0; c < 4; c++) acc[nt][c] = 0.f;

#pragma unroll 4
        for (int k0 = 0; k0 < 128; k0 += 8) {
            const uint32_t a0 = xs[(mb + g) * XS_STRIDE + k0 + tid4];
            const uint32_t a1 = xs[(mb + g + 8) * XS_STRIDE + k0 + tid4];
            const uint32_t a2 = xs[(mb + g) * XS_STRIDE + k0 + tid4 + 4];
            const uint32_t a3 = xs[(mb + g + 8) * XS_STRIDE + k0 + tid4 + 4];
#pragma unroll
            for (int nt = 0; nt < 4; nt++) {
                const uint32_t b0 = ws[(k0 + tid4) * WS_STRIDE + nb + nt * 8 + g];
                const uint32_t b1 = ws[(k0 + tid4 + 4) * WS_STRIDE + nb + nt * 8 + g];
                mma_tf32(acc[nt], a0, a1, a2, a3, b0, b1);
            }
        }

        // epilogue: add bias, write float2 per (row, n-tile)
        const int r0 = n0 + mb + g;
        const int r1 = r0 + 8;
#pragma unroll
        for (int nt = 0; nt < 4; nt++) {
            const int coll = nb + nt * 8 + tid4 * 2;     // within 64-col half
            const int colg = wcol0 + coll;               // within 128
            const float b0v = bs[coll];
            const float b1v = bs[coll + 1];
            if (r0 < N_NODES) {
                float2 v = make_float2(acc[nt][0] + b0v, acc[nt][1] + b1v);
                *(float2*)(gout + (size_t)r0 * 128 + colg) = v;
            }
            if (r1 < N_NODES) {
                float2 v = make_float2(acc[nt][2] + b0v, acc[nt][3] + b1v);
                *(float2*)(gout + (size_t)r1 * 128 + colg) = v;
            }
        }
    }
}

// ---------------- CSR build: histogram -> scan -> scatter --------------------
__global__ void hist_kernel(const int* __restrict__ etgt) {
    int i = blockIdx.x * blockDim.x + threadIdx.x;
    if (i < N_EDGES) atomicAdd(&g_count[etgt[i]], 1);
}

#define SCAN_THREADS 1024
__global__ void scan_kernel() {
    __shared__ int partial[SCAN_THREADS];
    const int t = threadIdx.x;
    const int CHUNK = (N_NODES + SCAN_THREADS - 1) / SCAN_THREADS;  // 49
    const int base = t * CHUNK;

    int s = 0;
    for (int i = 0; i < CHUNK; i++) {
        int idx = base + i;
        if (idx < N_NODES) s += g_count[idx];
    }
    partial[t] = s;
    __syncthreads();

    for (int off = 1; off < SCAN_THREADS; off <<= 1) {
        int u = (t >= off) ? partial[t - off] : 0;
        __syncthreads();
        partial[t] += u;
        __syncthreads();
    }

    int run = partial[t] - s;
    for (int i = 0; i < CHUNK; i++) {
        int idx = base + i;
        if (idx < N_NODES) {
            g_offset[idx] = run;
            g_cursor[idx] = run;
            run += g_count[idx];
        }
    }
    if (t == SCAN_THREADS - 1) g_offset[N_NODES] = partial[SCAN_THREADS - 1];
}

__global__ void scatter_kernel(const int* __restrict__ esrc,
                               const int* __restrict__ etgt) {
    int i = blockIdx.x * blockDim.x + threadIdx.x;
    if (i < N_EDGES) {
        int pos = atomicAdd(&g_cursor[etgt[i]], 1);
        g_src_sorted[pos] = esrc[i];
    }
}

// ---------------- Kernel 2: per-node gather (exact R9 known-good, MLP=4) -----
__global__ void __launch_bounds__(256)
gather_kernel(const float* __restrict__ attn, float* __restrict__ out) {
    __shared__ float a_s[128];
    if (threadIdx.x < 128) a_s[threadIdx.x] = attn[threadIdx.x];
    __syncthreads();

    const int node = (blockIdx.x * blockDim.x + threadIdx.x) >> 5;
    if (node >= N_NODES) return;
    const int lane = threadIdx.x & 31;
    const int part = lane & 3;
    const int h = lane >> 2;

    const float a0 = a_s[(part * 4 + 0) * 8 + h];
    const float a1 = a_s[(part * 4 + 1) * 8 + h];
    const float a2 = a_s[(part * 4 + 2) * 8 + h];
    const float a3 = a_s[(part * 4 + 3) * 8 + h];

    const float4 qv = *(const float4*)(g_q + (size_t)node * 128 + lane * 4);

    const int start = g_offset[node];
    const int end = g_offset[node + 1];

    float4 acc = make_float4(0.f, 0.f, 0.f, 0.f);
    float dsum = 0.f;

    for (int b = start; b < end; b += 32) {
        const int cnt = min(32, end - b);
        const int src_l = (lane < cnt) ? g_src_sorted[b + lane] : 0;

        int j = 0;
        for (; j + 4 <= cnt; j += 4) {
            const int s0 = __shfl_sync(0xffffffffu, src_l, j);
            const int s1 = __shfl_sync(0xffffffffu, src_l, j + 1);
            const int s2 = __shfl_sync(0xffffffffu, src_l, j + 2);
            const int s3 = __shfl_sync(0xffffffffu, src_l, j + 3);
            const float4 k0 = *(const float4*)(g_k + (size_t)s0 * 128 + lane * 4);
            const float4 k1 = *(const float4*)(g_k + (size_t)s1 * 128 + lane * 4);
            const float4 k2 = *(const float4*)(g_k + (size_t)s2 * 128 + lane * 4);
            const float4 k3 = *(const float4*)(g_k + (size_t)s3 * 128 + lane * 4);

            float p0 = lrelu(qv.x + k0.x) * a0 + lrelu(qv.y + k0.y) * a1 +
                       lrelu(qv.z + k0.z) * a2 + lrelu(qv.w + k0.w) * a3;
            float p1 = lrelu(qv.x + k1.x) * a0 + lrelu(qv.y + k1.y) * a1 +
                       lrelu(qv.z + k1.z) * a2 + lrelu(qv.w + k1.w) * a3;
            float p2 = lrelu(qv.x + k2.x) * a0 + lrelu(qv.y + k2.y) * a1 +
                       lrelu(qv.z + k2.z) * a2 + lrelu(qv.w + k2.w) * a3;
            float p3 = lrelu(qv.x + k3.x) * a0 + lrelu(qv.y + k3.y) * a1 +
                       lrelu(qv.z + k3.z) * a2 + lrelu(qv.w + k3.w) * a3;

            p0 += __shfl_xor_sync(0xffffffffu, p0, 1);
            p1 += __shfl_xor_sync(0xffffffffu, p1, 1);
            p2 += __shfl_xor_sync(0xffffffffu, p2, 1);
            p3 += __shfl_xor_sync(0xffffffffu, p3, 1);
            p0 += __shfl_xor_sync(0xffffffffu, p0, 2);
            p1 += __shfl_xor_sync(0xffffffffu, p1, 2);
            p2 += __shfl_xor_sync(0xffffffffu, p2, 2);
            p3 += __shfl_xor_sync(0xffffffffu, p3, 2);

            const float u0 = __expf(p0);
            const float u1 = __expf(p1);
            const float u2 = __expf(p2);
            const float u3 = __expf(p3);

            acc.x += u0 * k0.x + u1 * k1.x + u2 * k2.x + u3 * k3.x;
            acc.y += u0 * k0.y + u1 * k1.y + u2 * k2.y + u3 * k3.y;
            acc.z += u0 * k0.z + u1 * k1.z + u2 * k2.z + u3 * k3.z;
            acc.w += u0 * k0.w + u1 * k1.w + u2 * k2.w + u3 * k3.w;
            dsum += (u0 + u1) + (u2 + u3);
        }
        for (; j < cnt; j++) {
            const int s0 = __shfl_sync(0xffffffffu, src_l, j);
            const float4 k0 = *(const float4*)(g_k + (size_t)s0 * 128 + lane * 4);
            float p0 = lrelu(qv.x + k0.x) * a0 + lrelu(qv.y + k0.y) * a1 +
                       lrelu(qv.z + k0.z) * a2 + lrelu(qv.w + k0.w) * a3;
            p0 += __shfl_xor_sync(0xffffffffu, p0, 1);
            p0 += __shfl_xor_sync(0xffffffffu, p0, 2);
            const float u0 = __expf(p0);
            acc.x += u0 * k0.x;
            acc.y += u0 * k0.y;
            acc.z += u0 * k0.z;
            acc.w += u0 * k0.w;
            dsum += u0;
        }
    }

    const float inv = (dsum > 0.f) ? 1.f / dsum : 0.f;
    float4 o;
    o.x = fmaxf(acc.x * inv, 0.f);
    o.y = fmaxf(acc.y * inv, 0.f);
    o.z = fmaxf(acc.z * inv, 0.f);
    o.w = fmaxf(acc.w * inv, 0.f);
    *(float4*)(out + (size_t)node * 128 + lane * 4) = o;
}

// ---------------- launch (serial; GEMM first so ncu window hits gather) ------
extern "C" void kernel_launch(void* const* d_in, const int* in_sizes, int n_in,
                              void* d_out, int out_size) {
    const float* x    = (const float*)d_in[0];
    const float* wq   = (const float*)d_in[1];
    const float* bq   = (const float*)d_in[2];
    const float* wk   = (const float*)d_in[3];
    const float* bk   = (const float*)d_in[4];
    const float* attn = (const float*)d_in[5];
    const int*   esrc = (const int*)d_in[6];
    const int*   etgt = (const int*)d_in[7];
    float* out = (float*)d_out;

    // tensor-core Q/K GEMM first (independent of CSR): ~71KB smem, 3 CTAs/SM
    static const size_t gemm_smem =
        (128 * WS_STRIDE + GEMM_TILE_N * XS_STRIDE) * 4 + 64 * 4;
    cudaFuncSetAttribute(qk_gemm_tc_kernel,
                         cudaFuncAttributeMaxDynamicSharedMemorySize,
                         (int)gemm_smem);
    dim3 gemm_grid(GEMM_GRID_X, 4);
    qk_gemm_tc_kernel<<<gemm_grid, GEMM_BLOCK, gemm_smem>>>(x, wq, bq, wk, bk);

    // CSR build (zero histogram via symbol address query, no alloc)
    void* count_ptr = nullptr;
    cudaGetSymbolAddress(&count_ptr, g_count);
    cudaMemsetAsync(count_ptr, 0, N_NODES * sizeof(int), 0);
    hist_kernel<<<(N_EDGES + 255) / 256, 256>>>(etgt);
    scan_kernel<<<1, SCAN_THREADS>>>();
    scatter_kernel<<<(N_EDGES + 255) / 256, 256>>>(esrc, etgt);

    // per-node gather: one warp per node, 8 nodes per 256-thread block
    gather_kernel<<<(N_NODES * 32 + 255) / 256, 256>>>(attn, out);
}